// round 2
// baseline (speedup 1.0000x reference)
#include <cuda_runtime.h>

#define L      8192
#define KK     31
#define HALF   15
#define NT     256
#define C      16            // outputs per segment per thread; 2 segments -> 32 outputs/thread
#define HALO   16
#define USEG   (L + 2*HALO)                 // 8224 logical padded length
#define PHYS   (USEG + (USEG >> 4) + 8)     // 8746 floats, +(u>>4) padding kills bank conflicts
#define EPS    1e-6f

// physical index in padded SMEM row: logical i in [-HALO, L+HALO)
__device__ __forceinline__ int ph(int i) {
    int u = i + HALO;
    return u + (u >> 4);
}

__device__ __forceinline__ unsigned long long pk2(float lo, float hi) {
    unsigned long long r;
    asm("mov.b64 %0, {%1, %2};" : "=l"(r) : "f"(lo), "f"(hi));
    return r;
}
__device__ __forceinline__ void upk2(unsigned long long v, float &lo, float &hi) {
    asm("mov.b64 {%0, %1}, %2;" : "=f"(lo), "=f"(hi) : "l"(v));
}
// d = a*b + d  on packed f32x2 (sm_100+; ptxas never auto-fuses this — PTX only)
__device__ __forceinline__ void fma2(unsigned long long &d, unsigned long long a, unsigned long long b) {
    asm("fma.rn.f32x2 %0, %1, %2, %0;" : "+l"(d) : "l"(a), "l"(b));
}

// 31-tap conv on packed (segA, segB) lanes. src is padded SMEM row with zeroed halos.
__device__ __forceinline__ void conv_pairs(const float* __restrict__ src,
                                           const float* __restrict__ taps,
                                           int bA, int bB,
                                           unsigned long long acc[C]) {
    unsigned long long r[C + KK - 1];            // 46-pair sliding window in registers
    #pragma unroll
    for (int k = 0; k < C + KK - 1; ++k)
        r[k] = pk2(src[ph(bA - HALF + k)], src[ph(bB - HALF + k)]);
    #pragma unroll
    for (int p = 0; p < C; ++p) acc[p] = 0ull;
    #pragma unroll
    for (int j = 0; j < KK; ++j) {
        const float w = taps[j];                 // LDS broadcast (all lanes same addr)
        const unsigned long long wp = pk2(w, w);
        #pragma unroll
        for (int p = 0; p < C; ++p)
            fma2(acc[p], r[p + j], wp);          // window shifts by whole pairs: no repack
    }
}

__global__ void __launch_bounds__(NT)
drl_kernel(const float* __restrict__ m,
           const float* __restrict__ psf,
           const float* __restrict__ alpha,
           float* __restrict__ out,
           int nlayers) {
    extern __shared__ float smbuf[];
    float* S = smbuf;                // current estimate s, padded + halo
    float* T = smbuf + PHYS;         // scratch: ratio, padded + halo
    __shared__ float Wf[KK], Wr[KK];

    const int tid = threadIdx.x;
    const int row = blockIdx.x;

    if (tid < KK) {
        Wf[tid] = psf[tid];
        Wr[tid] = psf[KK - 1 - tid]; // flipped kernel for correlation pass
    }

    // init: S = 0.5 inside, 0 in halos; T halos = 0 (stay 0 forever)
    for (int u = tid; u < USEG; u += NT) {
        int p = u + (u >> 4);
        bool inside = (u >= HALO) && (u < HALO + L);
        S[p] = inside ? 0.5f : 0.0f;
        T[p] = 0.0f;
    }

    const int bA = tid * C;
    const int bB = bA + (L / 2);

    // x row chunk lives in registers for the whole kernel (read once from HBM)
    unsigned long long xr[C];
    const float* mrow = m + (size_t)row * L;
    #pragma unroll
    for (int p = 0; p < C; ++p)
        xr[p] = pk2(mrow[bA + p], mrow[bB + p]);

    __syncthreads();

    for (int layer = 0; layer < nlayers; ++layer) {
        const float a = alpha[layer];

        // ---- pass 1: s_conv = conv(S, w) + EPS ; ratio = x / s_conv -> T ----
        {
            unsigned long long acc[C];
            conv_pairs(S, Wf, bA, bB, acc);
            #pragma unroll
            for (int p = 0; p < C; ++p) {
                float sa, sb, xa, xb;
                upk2(acc[p], sa, sb);
                upk2(xr[p], xa, xb);
                T[ph(bA + p)] = xa / (sa + EPS);
                T[ph(bB + p)] = xb / (sb + EPS);
            }
        }
        __syncthreads();

        // ---- pass 2: corr = max(conv(T, w_flip) + EPS, EPS); S = max(S * corr^a, EPS) ----
        {
            unsigned long long acc[C];
            conv_pairs(T, Wr, bA, bB, acc);
            #pragma unroll
            for (int p = 0; p < C; ++p) {
                float ca, cb;
                upk2(acc[p], ca, cb);
                ca = fmaxf(ca + EPS, EPS);
                cb = fmaxf(cb + EPS, EPS);
                if (a != 1.0f) {                 // warp-uniform: skipped for alpha==1
                    ca = __powf(ca, a);
                    cb = __powf(cb, a);
                }
                const int pa = ph(bA + p), pb = ph(bB + p);
                S[pa] = fmaxf(S[pa] * ca, EPS);
                S[pb] = fmaxf(S[pb] * cb, EPS);
            }
        }
        __syncthreads();
    }

    float* orow = out + (size_t)row * L;
    #pragma unroll
    for (int p = 0; p < C; ++p) {
        orow[bA + p] = S[ph(bA + p)];
        orow[bB + p] = S[ph(bB + p)];
    }
}

extern "C" void kernel_launch(void* const* d_in, const int* in_sizes, int n_in,
                              void* d_out, int out_size) {
    const float* m     = (const float*)d_in[0];
    const float* psf   = (const float*)d_in[1];
    const float* alpha = (const float*)d_in[2];
    float* out = (float*)d_out;

    const int nlayers = in_sizes[2];
    const int B = in_sizes[0] / L;
    const int smem_bytes = 2 * PHYS * (int)sizeof(float);

    cudaFuncSetAttribute(drl_kernel, cudaFuncAttributeMaxDynamicSharedMemorySize, smem_bytes);
    drl_kernel<<<B, NT, smem_bytes>>>(m, psf, alpha, out, nlayers);
}